// round 5
// baseline (speedup 1.0000x reference)
#include <cuda_runtime.h>
#include <cstdint>

#define GRID_N   64
#define GRID_N3  (64 * 64 * 64)      // 262144
#define BMAX     8
#define EPS_CLIP 1e-5f
#define EPS_DIV  1e-7f

// Scratch grids: interleaved {weight, weight*prob} per cell.
// 8 batches * 262144 cells * 8B = 16 MB (fits in L2).
__device__ __align__(16) float2 g_grid[BMAX * GRID_N3];

// ---------------------------------------------------------------------------
// Vector reductions (sm_90+): one instruction per 8B / 16B accumulate.
// ---------------------------------------------------------------------------
__device__ __forceinline__ void red_add_v2(float2* addr, float a, float b) {
    asm volatile("red.global.add.v2.f32 [%0], {%1, %2};"
                 :: "l"(addr), "f"(a), "f"(b) : "memory");
}

__device__ __forceinline__ void red_add_v4(float2* addr, float a, float b, float c, float d) {
    asm volatile("red.global.add.v4.f32 [%0], {%1, %2, %3, %4};"
                 :: "l"(addr), "f"(a), "f"(b), "f"(c), "f"(d) : "memory");
}

// ---------------------------------------------------------------------------
// Pass 1: zero the scratch grid (float4 stores, 16 MB)
// ---------------------------------------------------------------------------
__global__ void zero_kernel(int n4) {
    int i = blockIdx.x * blockDim.x + threadIdx.x;
    float4* g = reinterpret_cast<float4*>(g_grid);
    if (i < n4) g[i] = make_float4(0.f, 0.f, 0.f, 0.f);
}

// ---------------------------------------------------------------------------
// Pass 2: P2G scatter. One thread per particle, 27-tap quadratic B-spline.
// z-taps hit 3 consecutive cells -> pair into red.v4 + red.v2 in the interior.
// ---------------------------------------------------------------------------
__global__ void __launch_bounds__(256) scatter_kernel(
    const float* __restrict__ pos,
    const float* __restrict__ prob,
    const int*   __restrict__ bidx,
    int L)
{
    int i = blockIdx.x * blockDim.x + threadIdx.x;
    if (i >= L) return;

    const float hi = 1.0f - EPS_CLIP;
    float px = fminf(fmaxf(pos[3 * i + 0], EPS_CLIP), hi);
    float py = fminf(fmaxf(pos[3 * i + 1], EPS_CLIP), hi);
    float pz = fminf(fmaxf(pos[3 * i + 2], EPS_CLIP), hi);

    // Xp = pos / DX == pos * 64 exactly (DX = 1/64)
    float xp = px * 64.0f, yp = py * 64.0f, zp = pz * 64.0f;
    int bx = (int)xp, by = (int)yp, bz = (int)zp;   // floor (coords >= 0)
    float fx = xp - (float)bx;
    float fy = yp - (float)by;
    float fz = zp - (float)bz;

    float wx[3], wy[3], wz[3];
    wx[0] = 0.5f * (1.0f - fx) * (1.0f - fx);
    wx[1] = 0.75f - (fx - 0.5f) * (fx - 0.5f);
    wx[2] = 0.5f * fx * fx;
    wy[0] = 0.5f * (1.0f - fy) * (1.0f - fy);
    wy[1] = 0.75f - (fy - 0.5f) * (fy - 0.5f);
    wy[2] = 0.5f * fy * fy;
    wz[0] = 0.5f * (1.0f - fz) * (1.0f - fz);
    wz[1] = 0.75f - (fz - 0.5f) * (fz - 0.5f);
    wz[2] = 0.5f * fz * fz;

    float pr = prob[i];
    float2* grid = g_grid + (size_t)bidx[i] * GRID_N3;

    // bz is always in [0,63]; only the +/-1 z-taps can fall out of the box
    bool zlo = (bz >= 1);
    bool zhi = (bz <= 62);
    bool zint = zlo && zhi;

    #pragma unroll
    for (int ox = 0; ox < 3; ox++) {
        int tx = bx + ox - 1;
        if ((unsigned)tx >= (unsigned)GRID_N) continue;
        #pragma unroll
        for (int oy = 0; oy < 3; oy++) {
            int ty = by + oy - 1;
            if ((unsigned)ty >= (unsigned)GRID_N) continue;

            float wxy = wx[ox] * wy[oy];
            int cb = (tx * GRID_N + ty) * GRID_N + bz;   // middle z cell index
            float w0 = wxy * wz[0];
            float w1 = wxy * wz[1];
            float w2 = wxy * wz[2];

            if (zint) {
                float2* ptr = grid + (cb - 1);
                // global byte addr of ptr is 16B-aligned iff (cb-1) is even
                if (cb & 1) {
                    red_add_v4(ptr,     w0, w0 * pr, w1, w1 * pr);
                    red_add_v2(ptr + 2, w2, w2 * pr);
                } else {
                    red_add_v2(ptr,     w0, w0 * pr);
                    red_add_v4(ptr + 1, w1, w1 * pr, w2, w2 * pr);
                }
            } else {
                if (zlo) red_add_v2(grid + cb - 1, w0, w0 * pr);
                red_add_v2(grid + cb, w1, w1 * pr);
                if (zhi) red_add_v2(grid + cb + 1, w2, w2 * pr);
            }
        }
    }
}

// ---------------------------------------------------------------------------
// Pass 3: out = wp / (w + eps). Two cells per thread via float4 load.
// ---------------------------------------------------------------------------
__global__ void divide_kernel(float* __restrict__ out, int n2) {
    int i = blockIdx.x * blockDim.x + threadIdx.x;
    if (i >= n2) return;
    const float4* g = reinterpret_cast<const float4*>(g_grid);
    float4 v = g[i];                    // cells 2i (x,y) and 2i+1 (z,w)
    float2 r;
    r.x = v.y / (v.x + EPS_DIV);
    r.y = v.w / (v.z + EPS_DIV);
    reinterpret_cast<float2*>(out)[i] = r;
}

// ---------------------------------------------------------------------------
extern "C" void kernel_launch(void* const* d_in, const int* in_sizes, int n_in,
                              void* d_out, int out_size)
{
    const float* pos  = (const float*)d_in[0];
    const float* prob = (const float*)d_in[1];
    const int*   bidx = (const int*)d_in[2];
    int L = in_sizes[1];               // number of particles (prob element count)

    int n_cells = out_size;            // B * 64^3
    int n4 = n_cells / 2;              // float4 count for zeroing (2 float2 cells each)
    int n2 = n_cells / 2;              // cell pairs for divide

    zero_kernel<<<(n4 + 255) / 256, 256>>>(n4);
    scatter_kernel<<<(L + 255) / 256, 256>>>(pos, prob, bidx, L);
    divide_kernel<<<(n2 + 255) / 256, 256>>>((float*)d_out, n2);
}